// round 5
// baseline (speedup 1.0000x reference)
#include <cuda_runtime.h>
#include <stdint.h>

#define GRID_N   8
#define L_SITES  64
#define S_SIZE   9
#define N_PLAQ   64
#define LOCAL_D  2
#define M_DIM    128
#define BATCH    2048
#define N_PAT    512        // 2^9

#define NBLK     128        // <= 148 SMs: all blocks resident -> spin is safe
#define NTHR     512
#define BPB      16         // batches per block (16 warps)
#define ROW_STR  132        // padded row stride (floats): kills bank conflicts

// Scratch: T[p][pattern] = sum_m prod_s eps[bit_s, p, m, s]  (512 KB, L2-resident)
__device__ float    g_table[N_PLAQ * N_PAT];
__device__ unsigned g_done;          // reset to 0 each launch via memset node

__global__ __launch_bounds__(NTHR, 1)
void fused_kernel(const int* __restrict__ inputs,
                  const float* __restrict__ eps,
                  float* __restrict__ out)
{
    const int tid  = threadIdx.x;
    const int blk  = blockIdx.x;
    const int p    = blk >> 1;        // plaquette
    const int half = blk & 1;         // hi-range half: hi_global = half*16 + hl

    __shared__ __align__(16) float sSA[16 * ROW_STR];  // hi-half rows [hl][m]
    __shared__ __align__(16) float sSB[16 * ROW_STR];  // lo rows      [lo][m]
    __shared__ float sPart[2 * 256];                   // k-split partials

    // ---------------- Phase 1: partial products into shared ----------------
    {
        const int m    = tid & 127;
        const int part = tid >> 7;    // 0..3 -> 8 rows each
        const float* e0p = eps + ((size_t)(0 * N_PLAQ + p) * M_DIM + m) * S_SIZE;
        const float* e1p = eps + ((size_t)(1 * N_PLAQ + p) * M_DIM + m) * S_SIZE;
        float a0[S_SIZE], a1[S_SIZE];
        #pragma unroll
        for (int s = 0; s < S_SIZE; s++) { a0[s] = __ldg(e0p + s); a1[s] = __ldg(e1p + s); }

        if (part < 2) {
            const int base = part * 8;
            #pragma unroll
            for (int k = 0; k < 8; k++) {
                const int lo = base + k;
                float v = ((lo & 1) ? a1[0] : a0[0]);
                v *= ((lo & 2) ? a1[1] : a0[1]);
                v *= ((lo & 4) ? a1[2] : a0[2]);
                v *= ((lo & 8) ? a1[3] : a0[3]);
                sSB[lo * ROW_STR + m] = v;
            }
        } else {
            const int base = (part - 2) * 8;
            const float t8 = half ? a1[8] : a0[8];   // s8 bit = half
            #pragma unroll
            for (int k = 0; k < 8; k++) {
                const int hl = base + k;             // local hi (bits s4..s7)
                float v = ((hl & 1) ? a1[4] : a0[4]);
                v *= ((hl & 2) ? a1[5] : a0[5]);
                v *= ((hl & 4) ? a1[6] : a0[6]);
                v *= ((hl & 8) ? a1[7] : a0[7]);
                sSA[hl * ROW_STR + m] = v * t8;
            }
        }
    }
    __syncthreads();

    // ------------- Phase 2: 256 patterns, 2-way k-split dot products --------
    {
        const int q  = tid & 255;     // local pattern
        const int kc = tid >> 8;      // k-chunk 0/1 (64 floats each)
        const int hl = q >> 4;
        const int lo = q & 15;
        const float4* A = reinterpret_cast<const float4*>(sSA + hl * ROW_STR + kc * 64);
        const float4* B = reinterpret_cast<const float4*>(sSB + lo * ROW_STR + kc * 64);
        float acc = 0.0f;
        #pragma unroll
        for (int i = 0; i < 16; i++) {
            float4 a = A[i];
            float4 b = B[i];
            acc += a.x * b.x + a.y * b.y + a.z * b.z + a.w * b.w;
        }
        sPart[kc * 256 + q] = acc;
    }
    __syncthreads();

    if (tid < 256) {
        const int q    = tid;
        const int patg = ((half * 16 + (q >> 4)) << 4) | (q & 15);  // hi*16+lo
        g_table[p * N_PAT + patg] = sPart[q] + sPart[256 + q];
    }
    __threadfence();     // make table stores device-visible (release)
    __syncthreads();
    if (tid == 0) atomicAdd(&g_done, 1u);

    // ------- Lookup prefetch: patterns are table-independent, do them now ----
    const int lane = tid & 31;
    const int warp = tid >> 5;
    const int b    = blk * BPB + warp;

    const int* rowp = inputs + (size_t)b * L_SITES;
    const unsigned mlo = __ballot_sync(0xFFFFFFFFu, rowp[lane]      & 1);
    const unsigned mhi = __ballot_sync(0xFFFFFFFFu, rowp[lane + 32] & 1);

    int pats[2];
    #pragma unroll
    for (int pp = 0; pp < 2; pp++) {
        const int pl = lane + 32 * pp;
        const int i  = pl >> 3;
        const int j  = pl & 7;
        int pat = 0;
        #pragma unroll
        for (int di = 0; di < 3; di++) {
            const int r = (i + di) & 7;
            unsigned rb = (((r < 4) ? mlo : mhi) >> ((r & 3) * 8)) & 0xFFu;
            const unsigned dup = rb | (rb << 8);          // torus wraparound
            pat |= (int)((dup >> j) & 7u) << (3 * di);
        }
        pats[pp] = pat;
    }

    // ------------------------- Wait for full table --------------------------
    if (tid == 0) {
        while (atomicAdd(&g_done, 0u) < NBLK) __nanosleep(64);
    }
    __syncthreads();
    __threadfence();     // acquire before reading peer blocks' table entries

    float acc = __ldg(&g_table[lane * N_PAT + pats[0]])
              + __ldg(&g_table[(lane + 32) * N_PAT + pats[1]]);

    #pragma unroll
    for (int off = 16; off > 0; off >>= 1)
        acc += __shfl_xor_sync(0xFFFFFFFFu, acc, off);

    if (lane == 0) out[b] = acc;
}

// ---------------------------------------------------------------------------
extern "C" void kernel_launch(void* const* d_in, const int* in_sizes, int n_in,
                              void* d_out, int out_size)
{
    // Identify inputs by element count (all distinct):
    //   inputs: 2048*64 = 131072 (int32), plaquettes: 576 (int32, unused),
    //   epsilon: 2*64*128*9 = 147456 (float32)
    const int*   inputs = nullptr;
    const float* eps    = nullptr;
    for (int i = 0; i < n_in; i++) {
        if      (in_sizes[i] == BATCH * L_SITES) inputs = (const int*)d_in[i];
        else if (in_sizes[i] == LOCAL_D * N_PLAQ * M_DIM * S_SIZE)
                                                 eps    = (const float*)d_in[i];
    }
    float* out = (float*)d_out;

    // Reset the arrival counter (graph-capturable memset node; no allocation).
    void* done_ptr = nullptr;
    cudaGetSymbolAddress(&done_ptr, g_done);
    cudaMemsetAsync(done_ptr, 0, sizeof(unsigned));

    fused_kernel<<<NBLK, NTHR>>>(inputs, eps, out);
}

// round 6
// speedup vs baseline: 1.0685x; 1.0685x over previous
#include <cuda_runtime.h>
#include <stdint.h>

#define GRID_N   8
#define L_SITES  64
#define S_SIZE   9
#define N_PLAQ   64
#define LOCAL_D  2
#define M_DIM    128
#define BATCH    2048
#define N_PAT    512         // 2^9

#define ROW_STR  68          // padded row stride (floats) for 64-wide m-half

// Occupancy bitmasks: one 64-bit mask per batch (16 KB, L2-resident)
__device__ uint2 g_masks[BATCH];

// ---------------------------------------------------------------------------
// Kernel A: pack occupancies into bitmasks, zero the output.
// One warp per batch; 128 blocks x 512 threads.
// ---------------------------------------------------------------------------
__global__ __launch_bounds__(512)
void pack_kernel(const int* __restrict__ inputs, float* __restrict__ out)
{
    const int lane = threadIdx.x & 31;
    const int warp = threadIdx.x >> 5;
    const int b    = blockIdx.x * 16 + warp;

    const int* row = inputs + (size_t)b * L_SITES;
    const unsigned mlo = __ballot_sync(0xFFFFFFFFu, row[lane]      & 1);
    const unsigned mhi = __ballot_sync(0xFFFFFFFFu, row[lane + 32] & 1);
    if (lane == 0) {
        g_masks[b] = make_uint2(mlo, mhi);
        out[b] = 0.0f;
    }
}

// ---------------------------------------------------------------------------
// Kernel B: one block per (plaquette, m-half). Build the 512-entry pattern
// table for this slice ENTIRELY in shared, then scatter contributions to all
// 2048 outputs with atomicAdd. No global table, no cross-block sync.
// ---------------------------------------------------------------------------
__global__ __launch_bounds__(512, 1)
void plaq_kernel(const float* __restrict__ eps, float* __restrict__ out)
{
    const int tid = threadIdx.x;
    const int p   = blockIdx.x >> 1;      // plaquette
    const int mh  = blockIdx.x & 1;       // m-half: m in [mh*64, mh*64+64)

    __shared__ __align__(16) float sSA[32 * ROW_STR];  // [hi(s4..s8)][m] 8.5 KB
    __shared__ __align__(16) float sSB[16 * ROW_STR];  // [lo(s0..s3)][m] 4.3 KB
    __shared__ float sPart[4 * N_PAT];                 // k-chunk partials 8 KB
    __shared__ float sTab[N_PAT];                      // final slice table 2 KB

    // ---- Phase 1: partial subset-products into shared (128 threads) -------
    if (tid < 128) {
        const int m    = tid & 63;
        const int part = tid >> 6;        // 0: SB rows, 1: SA rows
        const int mg   = mh * 64 + m;
        const float* e0p = eps + ((size_t)(0 * N_PLAQ + p) * M_DIM + mg) * S_SIZE;
        const float* e1p = eps + ((size_t)(1 * N_PLAQ + p) * M_DIM + mg) * S_SIZE;
        float a0[S_SIZE], a1[S_SIZE];
        #pragma unroll
        for (int s = 0; s < S_SIZE; s++) { a0[s] = __ldg(e0p + s); a1[s] = __ldg(e1p + s); }

        if (part == 0) {
            #pragma unroll
            for (int lo = 0; lo < 16; lo++) {
                float v = ((lo & 1) ? a1[0] : a0[0]);
                v *= ((lo & 2) ? a1[1] : a0[1]);
                v *= ((lo & 4) ? a1[2] : a0[2]);
                v *= ((lo & 8) ? a1[3] : a0[3]);
                sSB[lo * ROW_STR + m] = v;
            }
        } else {
            #pragma unroll
            for (int hi = 0; hi < 32; hi++) {
                float v = ((hi & 1)  ? a1[4] : a0[4]);
                v *= ((hi & 2)  ? a1[5] : a0[5]);
                v *= ((hi & 4)  ? a1[6] : a0[6]);
                v *= ((hi & 8)  ? a1[7] : a0[7]);
                v *= ((hi & 16) ? a1[8] : a0[8]);
                sSA[hi * ROW_STR + m] = v;
            }
        }
    }
    __syncthreads();

    // ---- Phase 2: 2x2 pattern register-blocking, 4-way k-split ------------
    // thread = (quad, kc): quad -> (hi pair, lo pair), kc -> 16-float k-chunk.
    {
        const int quad = tid >> 2;            // 0..127
        const int kc   = tid & 3;             // 0..3
        const int hi0  = (quad >> 3) * 2;     // 0,2,..,30
        const int lo0  = (quad & 7) * 2;      // 0,2,..,14
        const float4* A0 = reinterpret_cast<const float4*>(sSA + hi0 * ROW_STR + kc * 16);
        const float4* A1 = reinterpret_cast<const float4*>(sSA + (hi0 + 1) * ROW_STR + kc * 16);
        const float4* B0 = reinterpret_cast<const float4*>(sSB + lo0 * ROW_STR + kc * 16);
        const float4* B1 = reinterpret_cast<const float4*>(sSB + (lo0 + 1) * ROW_STR + kc * 16);

        float a00 = 0.f, a01 = 0.f, a10 = 0.f, a11 = 0.f;
        #pragma unroll
        for (int i = 0; i < 4; i++) {
            const float4 x0 = A0[i], x1 = A1[i];
            const float4 y0 = B0[i], y1 = B1[i];
            a00 += x0.x*y0.x + x0.y*y0.y + x0.z*y0.z + x0.w*y0.w;
            a01 += x0.x*y1.x + x0.y*y1.y + x0.z*y1.z + x0.w*y1.w;
            a10 += x1.x*y0.x + x1.y*y0.y + x1.z*y0.z + x1.w*y0.w;
            a11 += x1.x*y1.x + x1.y*y1.y + x1.z*y1.z + x1.w*y1.w;
        }
        float* dst = sPart + kc * N_PAT;
        dst[(hi0    ) * 16 + lo0    ] = a00;
        dst[(hi0    ) * 16 + lo0 + 1] = a01;
        dst[(hi0 + 1) * 16 + lo0    ] = a10;
        dst[(hi0 + 1) * 16 + lo0 + 1] = a11;
    }
    __syncthreads();

    // ---- Combine k-chunks into the slice table ----------------------------
    sTab[tid] = sPart[tid] + sPart[N_PAT + tid]
              + sPart[2 * N_PAT + tid] + sPart[3 * N_PAT + tid];
    __syncthreads();

    // ---- Batch loop: 4 batches per thread, scatter via atomicAdd ----------
    const int i = p >> 3;
    const int j = p & 7;
    #pragma unroll
    for (int bb = 0; bb < 4; bb++) {
        const int b = bb * 512 + tid;
        const uint2 mk = g_masks[b];
        int pat = 0;
        #pragma unroll
        for (int di = 0; di < 3; di++) {
            const int r = (i + di) & 7;
            unsigned rb = (((r < 4) ? mk.x : mk.y) >> ((r & 3) * 8)) & 0xFFu;
            const unsigned dup = rb | (rb << 8);     // torus wraparound cols
            pat |= (int)((dup >> j) & 7u) << (3 * di);
        }
        atomicAdd(&out[b], sTab[pat]);
    }
}

// ---------------------------------------------------------------------------
extern "C" void kernel_launch(void* const* d_in, const int* in_sizes, int n_in,
                              void* d_out, int out_size)
{
    // Identify inputs by element count (all distinct):
    //   inputs: 2048*64 = 131072 (int32), plaquettes: 576 (int32, unused —
    //   the window is arithmetically fixed), epsilon: 147456 (float32)
    const int*   inputs = nullptr;
    const float* eps    = nullptr;
    for (int i = 0; i < n_in; i++) {
        if      (in_sizes[i] == BATCH * L_SITES) inputs = (const int*)d_in[i];
        else if (in_sizes[i] == LOCAL_D * N_PLAQ * M_DIM * S_SIZE)
                                                 eps    = (const float*)d_in[i];
    }
    float* out = (float*)d_out;

    pack_kernel<<<BATCH / 16, 512>>>(inputs, out);   // masks + zero out
    plaq_kernel<<<N_PLAQ * 2, 512>>>(eps, out);      // build slices + scatter
}